// round 14
// baseline (speedup 1.0000x reference)
#include <cuda_runtime.h>
#include <cuda_fp16.h>
#include <cstdint>

// Problem constants
constexpr int DM = 1024;    // d_model
constexpr int NH = 16;      // heads
constexpr int DH = 64;      // head dim
constexpr int BB = 2;       // batch
constexpr int SS = 2048;    // seq len
constexpr int MT = BB * SS; // 4096 tokens

// softmax scale folded into Q, in log2 domain: 1/sqrt(64) * log2(e)
constexpr float QSCALE = 0.18033688011112042f;

// ---------------------------------------------------------------------------
// Scratch (device globals -- no allocations allowed). All fp16 hi-only.
// ---------------------------------------------------------------------------
__device__ __half g_xh[MT * DM];
__device__ __half g_wqh[DM * DM], g_wkh[DM * DM], g_wvh[DM * DM], g_woh[DM * DM];
__device__ __half g_qh[MT * DM];   // pre-scaled by QSCALE
__device__ __half g_kh[MT * DM];
__device__ __half g_vh[MT * DM];
__device__ __half g_ah[MT * DM];

// ---------------------------------------------------------------------------
// PTX helpers (sm_80-baseline: cp.async, ldmatrix, mma.sync)
// ---------------------------------------------------------------------------
__device__ __forceinline__ uint32_t smem_to_u32(const void* p) {
    uint32_t a;
    asm("{ .reg .u64 t; cvta.to.shared.u64 t, %1; cvt.u32.u64 %0, t; }"
        : "=r"(a) : "l"(p));
    return a;
}
__device__ __forceinline__ void cp_async16(uint32_t dst, const void* src) {
    asm volatile("cp.async.cg.shared.global [%0], [%1], 16;"
                 :: "r"(dst), "l"(src) : "memory");
}
#define CP_COMMIT() asm volatile("cp.async.commit_group;" ::: "memory")
template <int N>
__device__ __forceinline__ void cp_wait() {
    asm volatile("cp.async.wait_group %0;" :: "n"(N) : "memory");
}
__device__ __forceinline__ void ldmx4(uint32_t (&r)[4], uint32_t addr) {
    asm volatile("ldmatrix.sync.aligned.m8n8.x4.shared.b16 {%0,%1,%2,%3}, [%4];"
                 : "=r"(r[0]), "=r"(r[1]), "=r"(r[2]), "=r"(r[3]) : "r"(addr));
}
__device__ __forceinline__ void ldmx4t(uint32_t (&r)[4], uint32_t addr) {
    asm volatile("ldmatrix.sync.aligned.m8n8.x4.trans.shared.b16 {%0,%1,%2,%3}, [%4];"
                 : "=r"(r[0]), "=r"(r[1]), "=r"(r[2]), "=r"(r[3]) : "r"(addr));
}
// fp32-accumulating HMMA
__device__ __forceinline__ void mma16816(float (&c)[4], const uint32_t (&a)[4],
                                         uint32_t b0, uint32_t b1) {
    asm volatile(
        "mma.sync.aligned.m16n8k16.row.col.f32.f16.f16.f32 "
        "{%0,%1,%2,%3}, {%4,%5,%6,%7}, {%8,%9}, {%0,%1,%2,%3};"
        : "+f"(c[0]), "+f"(c[1]), "+f"(c[2]), "+f"(c[3])
        : "r"(a[0]), "r"(a[1]), "r"(a[2]), "r"(a[3]), "r"(b0), "r"(b1));
}
// fp16-accumulating HMMA (rate probe): C/D = 2 regs of packed half2
__device__ __forceinline__ void mma16816h(uint32_t (&c)[2], const uint32_t (&a)[4],
                                          uint32_t b0, uint32_t b1) {
    asm volatile(
        "mma.sync.aligned.m16n8k16.row.col.f16.f16.f16.f16 "
        "{%0,%1}, {%2,%3,%4,%5}, {%6,%7}, {%0,%1};"
        : "+r"(c[0]), "+r"(c[1])
        : "r"(a[0]), "r"(a[1]), "r"(a[2]), "r"(a[3]), "r"(b0), "r"(b1));
}
__device__ __forceinline__ float ex2f(float x) {
    float r;
    asm("ex2.approx.ftz.f32 %0, %1;" : "=f"(r) : "f"(x));
    return r;
}
__device__ __forceinline__ uint32_t h2ex2(uint32_t x) {
    uint32_t r;
    asm("ex2.approx.f16x2 %0, %1;" : "=r"(r) : "r"(x));
    return r;
}
__device__ __forceinline__ uint32_t hmax2u(uint32_t a, uint32_t b) {
    __half2 r = __hmax2(*reinterpret_cast<__half2*>(&a),
                        *reinterpret_cast<__half2*>(&b));
    return *reinterpret_cast<uint32_t*>(&r);
}
__device__ __forceinline__ uint32_t pack_h2(float x, float y) {
    __half2 h = __floats2half2_rn(x, y);
    return *reinterpret_cast<uint32_t*>(&h);
}
__device__ __forceinline__ float2 h2f2(uint32_t p) {
    return __half22float2(*reinterpret_cast<__half2*>(&p));
}

// Tile swizzle for 128B rows (64 halfs), 8 chunks of 16B — conflict-free for
// cp.async writes and every ldmatrix phase.
__device__ __forceinline__ uint32_t atile_off(int row, int c) {
    return (uint32_t)(row * 128 + (((c ^ (row & 7)) & 7) << 4));
}

// ---------------------------------------------------------------------------
// Input conversion (all hi-only): y 0..3 weights, y 4..7 x quarters.
// ---------------------------------------------------------------------------
__global__ __launch_bounds__(256) void cvt_all(
    const float* __restrict__ x,
    const float* __restrict__ Wq, const float* __restrict__ Wk,
    const float* __restrict__ Wv, const float* __restrict__ Wo) {
    const int y = blockIdx.y;
    const int i = blockIdx.x * 256 + threadIdx.x;
    const float* src;
    __half* dst;
    size_t base;
    if (y < 4) {
        src = (y == 0) ? Wq : (y == 1) ? Wk : (y == 2) ? Wv : Wo;
        dst = (y == 0) ? g_wqh : (y == 1) ? g_wkh : (y == 2) ? g_wvh : g_woh;
        base = 0;
    } else {
        src = x;
        dst = g_xh;
        base = (size_t)(y - 4) * (MT * DM / 4);
    }
    float4 v = ((const float4*)(src + base))[i];
    *(uint2*)(dst + base + (size_t)i * 4) =
        make_uint2(pack_h2(v.x, v.y), pack_h2(v.z, v.w));
}

// ---------------------------------------------------------------------------
// Single-pass fp16 tensor-core GEMM (fp32 acc): Y = A @ B^T.
// 128x128 CTA tile, BK=64, 3-stage cp.async, one sync per chunk.
// 256 threads = 8 warps, warp tile 64x32, 2 CTAs/SM. (unchanged from R11)
// ---------------------------------------------------------------------------
constexpr int GSTAGE = 32768;
constexpr int GEMM_SMEM = 3 * GSTAGE;   // 98304

__device__ __forceinline__ void stage_load(
    uint32_t sbase, int st, const __half* __restrict__ Ah,
    const __half* __restrict__ Bh, int bm, int bn, int k0, int tid)
{
    const uint32_t base = sbase + st * GSTAGE;
#pragma unroll
    for (int i = 0; i < 8; i++) {
        int idx = tid + 256 * i;          // 0..2047
        int pl  = idx >> 10;              // 0:A 1:B
        int ci  = idx & 1023;
        int row = ci >> 3;                // 0..127
        int c   = ci & 7;                 // 16B chunk within 128B row
        const __half* src = pl ? Bh : Ah;
        int rowbase = pl ? bn : bm;
        cp_async16(base + pl * 16384 + atile_off(row, c),
                   src + (size_t)(rowbase + row) * 1024 + k0 + c * 8);
    }
}

__device__ __forceinline__ void mma_gemm_body(
    const __half* __restrict__ Ah, const __half* __restrict__ Bh,
    float* __restrict__ Yf32, const float* __restrict__ bias,
    __half* __restrict__ Yh, float oscale)
{
    extern __shared__ char smem[];
    const uint32_t sbase = smem_to_u32(smem);
    const int tid  = threadIdx.x;
    const int wid  = tid >> 5;
    const int lane = tid & 31;
    const int m_base = (wid & 1) * 64;    // 2 m-halves
    const int n_base = (wid >> 1) * 32;   // 4 n-quarters
    const int bm = blockIdx.y * 128;
    const int bn = blockIdx.x * 128;

    float acc[4][4][4];
#pragma unroll
    for (int mt = 0; mt < 4; mt++)
#pragma unroll
        for (int nt = 0; nt < 4; nt++)
#pragma unroll
            for (int i = 0; i < 4; i++) acc[mt][nt][i] = 0.f;

    stage_load(sbase, 0, Ah, Bh, bm, bn, 0, tid);  CP_COMMIT();
    stage_load(sbase, 1, Ah, Bh, bm, bn, 64, tid); CP_COMMIT();

    const int br  = lane & 7;
    const int bc0 = (lane >> 3) & 1;
    const int bro = (lane >> 4) << 3;

    for (int kc = 0; kc < 16; kc++) {
        if (kc < 15) cp_wait<1>(); else cp_wait<0>();
        __syncthreads();
        if (kc + 2 < 16) {
            stage_load(sbase, (kc + 2) % 3, Ah, Bh, bm, bn, (kc + 2) * 64, tid);
            CP_COMMIT();
        }

        const uint32_t st = sbase + (kc % 3) * GSTAGE;

        uint32_t bh[2][2][4];
#pragma unroll
        for (int ng = 0; ng < 2; ng++) {
            int row = n_base + ng * 16 + br + bro;
            ldmx4(bh[0][ng], st + 16384 + atile_off(row, bc0));
        }

#pragma unroll
        for (int s = 0; s < 4; s++) {
            uint32_t ah[4][4];
            {
                int r   = lane & 7;
                int sel = lane >> 3;
                int c   = 2 * s + (sel >> 1);
#pragma unroll
                for (int mt = 0; mt < 4; mt++) {
                    int row = m_base + mt * 16 + r + ((sel & 1) << 3);
                    ldmx4(ah[mt], st + atile_off(row, c));
                }
            }
            if (s < 3) {
                int c = 2 * (s + 1) + bc0;
#pragma unroll
                for (int ng = 0; ng < 2; ng++) {
                    int row = n_base + ng * 16 + br + bro;
                    ldmx4(bh[(s + 1) & 1][ng], st + 16384 + atile_off(row, c));
                }
            }
            const int cb = s & 1;
#pragma unroll
            for (int mt = 0; mt < 4; mt++)
#pragma unroll
                for (int nt = 0; nt < 4; nt++) {
                    int g = nt >> 1, o = (nt & 1) * 2;
                    mma16816(acc[mt][nt], ah[mt], bh[cb][g][o], bh[cb][g][o + 1]);
                }
        }
    }

    const int gid = lane >> 2;
    const int tig = lane & 3;
#pragma unroll
    for (int mt = 0; mt < 4; mt++) {
#pragma unroll
        for (int nt = 0; nt < 4; nt++) {
            int row0 = bm + m_base + mt * 16 + gid;
            int col0 = bn + n_base + nt * 8 + tig * 2;
            if (Yf32) {
                float b0 = bias ? bias[col0]     : 0.f;
                float b1 = bias ? bias[col0 + 1] : 0.f;
                float2 v0 = make_float2(acc[mt][nt][0] + b0, acc[mt][nt][1] + b1);
                float2 v1 = make_float2(acc[mt][nt][2] + b0, acc[mt][nt][3] + b1);
                *(float2*)(Yf32 + (size_t)row0 * 1024 + col0)       = v0;
                *(float2*)(Yf32 + (size_t)(row0 + 8) * 1024 + col0) = v1;
            } else {
                uint32_t h0 = pack_h2(acc[mt][nt][0] * oscale, acc[mt][nt][1] * oscale);
                uint32_t h1 = pack_h2(acc[mt][nt][2] * oscale, acc[mt][nt][3] * oscale);
                *(uint32_t*)(Yh + (size_t)row0 * 1024 + col0)       = h0;
                *(uint32_t*)(Yh + (size_t)(row0 + 8) * 1024 + col0) = h1;
            }
        }
    }
}

__global__ __launch_bounds__(256, 2) void qkv_mma() {
    if (blockIdx.z == 0)
        mma_gemm_body(g_xh, g_wqh, nullptr, nullptr, g_qh, QSCALE);
    else if (blockIdx.z == 1)
        mma_gemm_body(g_xh, g_wkh, nullptr, nullptr, g_kh, 1.f);
    else
        mma_gemm_body(g_xh, g_wvh, nullptr, nullptr, g_vh, 1.f);
}

__global__ __launch_bounds__(256, 2) void o_mma(const float* __restrict__ bo,
                                                float* __restrict__ out) {
    mma_gemm_body(g_ah, g_woh, out, bo, nullptr, 1.f);
}

// ---------------------------------------------------------------------------
// Single-pass fp16 causal flash attention.
// NEW: QK^T uses fp16-accumulating HMMA (rt8 rate probe; K=64 depth only,
// log2-domain scores |S|<~15 so fp16 acc adds ~2e-4). PV stays fp32 acc.
// grid = (S/128, B*H), 256 threads (8 warps, warp = 16 q rows), 2 CTAs/SM.
// ---------------------------------------------------------------------------
constexpr int ASTAGE = 16384;
constexpr int ATTN_SMEM = 16384 + 3 * ASTAGE;  // 65536

__device__ __forceinline__ void attn_load_kv(uint32_t sb, int stage, int kv0,
                                             size_t headoff, int tid) {
#pragma unroll
    for (int i = 0; i < 4; i++) {
        int idx = tid + 256 * i;        // 0..1023
        int pl  = idx >> 9;             // 0:K 1:V
        int ci  = idx & 511;
        int r   = ci >> 3;
        int c   = ci & 7;
        const __half* base = pl ? g_vh : g_kh;
        cp_async16(sb + 16384 + stage * ASTAGE + pl * 8192 + atile_off(r, c),
                   base + headoff + (size_t)(kv0 + r) * DM + c * 8);
    }
    CP_COMMIT();
}

__global__ __launch_bounds__(256, 2) void attn_mma() {
    extern __shared__ char smem[];
    const uint32_t sb = smem_to_u32(smem);
    const int tid  = threadIdx.x;
    const int wid  = tid >> 5;
    const int lane = tid & 31;
    const int gid  = lane >> 2;
    const int tig  = lane & 3;
    const int bx   = gridDim.x - 1 - blockIdx.x;   // heavy blocks first
    const int bh   = blockIdx.y;
    const int b    = bh >> 4;
    const int h    = bh & 15;
    const int qb   = bx * 128;
    const int qw   = wid * 16;
    const size_t headoff = (size_t)(b * SS) * DM + h * 64;

#pragma unroll
    for (int i = 0; i < 4; i++) {
        int idx = tid + 256 * i;
        int r   = idx >> 3;
        int c   = idx & 7;
        cp_async16(sb + atile_off(r, c),
                   g_qh + headoff + (size_t)(qb + r) * DM + c * 8);
    }
    CP_COMMIT();

    float o[8][4];
#pragma unroll
    for (int nt = 0; nt < 8; nt++)
#pragma unroll
        for (int i = 0; i < 4; i++) o[nt][i] = 0.f;
    float m0 = -1e30f, m1 = -1e30f, l0 = 0.f, l1 = 0.f;

    const int ntiles = 2 * bx + 2;
    attn_load_kv(sb, 0, 0, headoff, tid);
    attn_load_kv(sb, 1, 64, headoff, tid);

    for (int t = 0; t < ntiles; t++) {
        if (t + 1 < ntiles) cp_wait<1>(); else cp_wait<0>();
        __syncthreads();
        if (t + 2 < ntiles)
            attn_load_kv(sb, (t + 2) % 3, (t + 2) * 64, headoff, tid);

        const uint32_t kst = sb + 16384 + (t % 3) * ASTAGE;

        // ---- S = Q * K^T (log2 units), fp16 accumulators ----
        uint32_t sfh[8][2];
#pragma unroll
        for (int jt = 0; jt < 8; jt++) { sfh[jt][0] = 0u; sfh[jt][1] = 0u; }

#pragma unroll
        for (int kc = 0; kc < 4; kc++) {
            uint32_t qh[4];
            {
                int r = lane & 7, sel = lane >> 3;
                int row = qw + r + ((sel & 1) << 3);
                int c = kc * 2 + (sel >> 1);
                ldmx4(qh, sb + atile_off(row, c));
            }
#pragma unroll
            for (int g2 = 0; g2 < 4; g2++) {
                uint32_t kh[4];
                {
                    int r = lane & 7;
                    int row = g2 * 16 + r + ((lane >> 4) << 3);
                    int c = kc * 2 + ((lane >> 3) & 1);
                    ldmx4(kh, kst + atile_off(row, c));
                }
                mma16816h(sfh[g2 * 2 + 0], qh, kh[0], kh[1]);
                mma16816h(sfh[g2 * 2 + 1], qh, kh[2], kh[3]);
            }
        }

        // Promote to fp32 for masking + softmax.
        // Layout: sfh[jt][0] = {c0,c1} (row gid), sfh[jt][1] = {c2,c3} (row gid+8)
        float sf[8][4];
#pragma unroll
        for (int jt = 0; jt < 8; jt++) {
            float2 f01 = h2f2(sfh[jt][0]);
            float2 f23 = h2f2(sfh[jt][1]);
            sf[jt][0] = f01.x; sf[jt][1] = f01.y;
            sf[jt][2] = f23.x; sf[jt][3] = f23.y;
        }

        // ---- causal mask (diagonal tiles only) ----
        if (t >= 2 * bx) {
            const int kv0 = t * 64;
            const int r0 = qb + qw + gid, r1 = r0 + 8;
#pragma unroll
            for (int jt = 0; jt < 8; jt++) {
                int col = kv0 + jt * 8 + tig * 2;
                if (col     > r0) sf[jt][0] = -1e30f;
                if (col + 1 > r0) sf[jt][1] = -1e30f;
                if (col     > r1) sf[jt][2] = -1e30f;
                if (col + 1 > r1) sf[jt][3] = -1e30f;
            }
        }

        // ---- online softmax (base-2), f16x2 exp ----
        float tm0 = -1e30f, tm1 = -1e30f;
#pragma unroll
        for (int jt = 0; jt < 8; jt++) {
            tm0 = fmaxf(tm0, fmaxf(sf[jt][0], sf[jt][1]));
            tm1 = fmaxf(tm1, fmaxf(sf[jt][2], sf[jt][3]));
        }
        uint32_t tm2 = pack_h2(tm0, tm1);
        tm2 = hmax2u(tm2, __shfl_xor_sync(0xFFFFFFFFu, tm2, 1));
        tm2 = hmax2u(tm2, __shfl_xor_sync(0xFFFFFFFFu, tm2, 2));
        float2 tmf = h2f2(tm2);

        float mn0 = fmaxf(fmaxf(m0, tmf.x), -1e4f);
        float mn1 = fmaxf(fmaxf(m1, tmf.y), -1e4f);
        float c0 = ex2f(m0 - mn0);
        float c1 = ex2f(m1 - mn1);
        m0 = mn0; m1 = mn1;

        uint32_t ph[16];
        float rs0 = 0.f, rs1 = 0.f;
#pragma unroll
        for (int jt = 0; jt < 8; jt++) {
            uint32_t p01 = h2ex2(pack_h2(sf[jt][0] - mn0, sf[jt][1] - mn0));
            uint32_t p23 = h2ex2(pack_h2(sf[jt][2] - mn1, sf[jt][3] - mn1));
            ph[jt * 2]     = p01;
            ph[jt * 2 + 1] = p23;
            float2 f01 = h2f2(p01);
            float2 f23 = h2f2(p23);
            rs0 += f01.x + f01.y;
            rs1 += f23.x + f23.y;
        }
        rs0 += __shfl_xor_sync(0xFFFFFFFFu, rs0, 1);
        rs0 += __shfl_xor_sync(0xFFFFFFFFu, rs0, 2);
        rs1 += __shfl_xor_sync(0xFFFFFFFFu, rs1, 1);
        rs1 += __shfl_xor_sync(0xFFFFFFFFu, rs1, 2);
        l0 = l0 * c0 + rs0;
        l1 = l1 * c1 + rs1;

#pragma unroll
        for (int nt = 0; nt < 8; nt++) {
            o[nt][0] *= c0; o[nt][1] *= c0;
            o[nt][2] *= c1; o[nt][3] *= c1;
        }

        // ---- O += P * V (fp32 acc) ----
#pragma unroll
        for (int kc = 0; kc < 4; kc++) {
            uint32_t pa[4] = {ph[4 * kc], ph[4 * kc + 1],
                              ph[4 * kc + 2], ph[4 * kc + 3]};
#pragma unroll
            for (int dg = 0; dg < 4; dg++) {
                uint32_t vh[4];
                {
                    int r = lane & 7;
                    int row = kc * 16 + r + (((lane >> 3) & 1) << 3);
                    int c = dg * 2 + (lane >> 4);
                    ldmx4t(vh, kst + 8192 + atile_off(row, c));
                }
                mma16816(o[dg * 2 + 0], pa, vh[0], vh[1]);
                mma16816(o[dg * 2 + 1], pa, vh[2], vh[3]);
            }
        }
    }

    const float inv0 = 1.f / l0;
    const float inv1 = 1.f / l1;
    const size_t tok0 = (size_t)(b * SS + qb + qw + gid) * DM;
#pragma unroll
    for (int nt = 0; nt < 8; nt++) {
        int col = h * 64 + nt * 8 + tig * 2;
        *(uint32_t*)(g_ah + tok0 + col) =
            pack_h2(o[nt][0] * inv0, o[nt][1] * inv0);
        *(uint32_t*)(g_ah + tok0 + 8 * DM + col) =
            pack_h2(o[nt][2] * inv1, o[nt][3] * inv1);
    }
}

// ---------------------------------------------------------------------------
extern "C" void kernel_launch(void* const* d_in, const int* in_sizes, int n_in,
                              void* d_out, int out_size)
{
    const float* x  = (const float*)d_in[0];
    const float* Wq = (const float*)d_in[1];
    const float* Wk = (const float*)d_in[2];
    const float* Wv = (const float*)d_in[3];
    const float* Wo = (const float*)d_in[4];
    const float* bo = (const float*)d_in[5];
    float* out = (float*)d_out;

    cudaFuncSetAttribute(qkv_mma,  cudaFuncAttributeMaxDynamicSharedMemorySize, GEMM_SMEM);
    cudaFuncSetAttribute(o_mma,    cudaFuncAttributeMaxDynamicSharedMemorySize, GEMM_SMEM);
    cudaFuncSetAttribute(attn_mma, cudaFuncAttributeMaxDynamicSharedMemorySize, ATTN_SMEM);

    cvt_all<<<dim3(1024, 8), 256>>>(x, Wq, Wk, Wv, Wo);

    dim3 gqkv(DM / 128, MT / 128, 3);
    qkv_mma<<<gqkv, 256, GEMM_SMEM>>>();

    dim3 gattn(SS / 128, BB * NH);
    attn_mma<<<gattn, 256, ATTN_SMEM>>>();

    dim3 go(DM / 128, MT / 128);
    o_mma<<<go, 256, GEMM_SMEM>>>(bo, out);
}

// round 15
// speedup vs baseline: 1.0041x; 1.0041x over previous
#include <cuda_runtime.h>
#include <cuda_fp16.h>
#include <cstdint>

// Problem constants
constexpr int DM = 1024;    // d_model
constexpr int NH = 16;      // heads
constexpr int DH = 64;      // head dim
constexpr int BB = 2;       // batch
constexpr int SS = 2048;    // seq len
constexpr int MT = BB * SS; // 4096 tokens

// softmax scale folded into Q, in log2 domain: 1/sqrt(64) * log2(e)
constexpr float QSCALE = 0.18033688011112042f;

// ---------------------------------------------------------------------------
// Scratch (device globals -- no allocations allowed). All fp16 hi-only.
// ---------------------------------------------------------------------------
__device__ __half g_xh[MT * DM];
__device__ __half g_wqh[DM * DM], g_wkh[DM * DM], g_wvh[DM * DM], g_woh[DM * DM];
__device__ __half g_qh[MT * DM];   // pre-scaled by QSCALE
__device__ __half g_kh[MT * DM];
__device__ __half g_vh[MT * DM];
__device__ __half g_ah[MT * DM];

// ---------------------------------------------------------------------------
// PTX helpers (sm_80-baseline: cp.async, ldmatrix, mma.sync)
// ---------------------------------------------------------------------------
__device__ __forceinline__ uint32_t smem_to_u32(const void* p) {
    uint32_t a;
    asm("{ .reg .u64 t; cvta.to.shared.u64 t, %1; cvt.u32.u64 %0, t; }"
        : "=r"(a) : "l"(p));
    return a;
}
__device__ __forceinline__ void cp_async16(uint32_t dst, const void* src) {
    asm volatile("cp.async.cg.shared.global [%0], [%1], 16;"
                 :: "r"(dst), "l"(src) : "memory");
}
#define CP_COMMIT() asm volatile("cp.async.commit_group;" ::: "memory")
template <int N>
__device__ __forceinline__ void cp_wait() {
    asm volatile("cp.async.wait_group %0;" :: "n"(N) : "memory");
}
__device__ __forceinline__ void ldmx4(uint32_t (&r)[4], uint32_t addr) {
    asm volatile("ldmatrix.sync.aligned.m8n8.x4.shared.b16 {%0,%1,%2,%3}, [%4];"
                 : "=r"(r[0]), "=r"(r[1]), "=r"(r[2]), "=r"(r[3]) : "r"(addr));
}
__device__ __forceinline__ void ldmx4t(uint32_t (&r)[4], uint32_t addr) {
    asm volatile("ldmatrix.sync.aligned.m8n8.x4.trans.shared.b16 {%0,%1,%2,%3}, [%4];"
                 : "=r"(r[0]), "=r"(r[1]), "=r"(r[2]), "=r"(r[3]) : "r"(addr));
}
__device__ __forceinline__ void mma16816(float (&c)[4], const uint32_t (&a)[4],
                                         uint32_t b0, uint32_t b1) {
    asm volatile(
        "mma.sync.aligned.m16n8k16.row.col.f32.f16.f16.f32 "
        "{%0,%1,%2,%3}, {%4,%5,%6,%7}, {%8,%9}, {%0,%1,%2,%3};"
        : "+f"(c[0]), "+f"(c[1]), "+f"(c[2]), "+f"(c[3])
        : "r"(a[0]), "r"(a[1]), "r"(a[2]), "r"(a[3]), "r"(b0), "r"(b1));
}
__device__ __forceinline__ float ex2f(float x) {
    float r;
    asm("ex2.approx.ftz.f32 %0, %1;" : "=f"(r) : "f"(x));
    return r;
}
__device__ __forceinline__ uint32_t h2ex2(uint32_t x) {
    uint32_t r;
    asm("ex2.approx.f16x2 %0, %1;" : "=r"(r) : "r"(x));
    return r;
}
__device__ __forceinline__ uint32_t hmax2u(uint32_t a, uint32_t b) {
    __half2 r = __hmax2(*reinterpret_cast<__half2*>(&a),
                        *reinterpret_cast<__half2*>(&b));
    return *reinterpret_cast<uint32_t*>(&r);
}
__device__ __forceinline__ uint32_t pack_h2(float x, float y) {
    __half2 h = __floats2half2_rn(x, y);
    return *reinterpret_cast<uint32_t*>(&h);
}
__device__ __forceinline__ float2 h2f2(uint32_t p) {
    return __half22float2(*reinterpret_cast<__half2*>(&p));
}

// Tile swizzle for 128B rows (64 halfs), 8 chunks of 16B — conflict-free for
// cp.async writes and every ldmatrix phase.
__device__ __forceinline__ uint32_t atile_off(int row, int c) {
    return (uint32_t)(row * 128 + (((c ^ (row & 7)) & 7) << 4));
}

// ---------------------------------------------------------------------------
// Input conversion (all hi-only): y 0..3 weights, y 4..7 x quarters.
// 2 float4 per thread for ILP (latency-bound kernel).
// ---------------------------------------------------------------------------
__global__ __launch_bounds__(256) void cvt_all(
    const float* __restrict__ x,
    const float* __restrict__ Wq, const float* __restrict__ Wk,
    const float* __restrict__ Wv, const float* __restrict__ Wo) {
    const int y = blockIdx.y;
    const int i = blockIdx.x * 256 + threadIdx.x;   // 0..131071
    const float* src;
    __half* dst;
    size_t base;
    if (y < 4) {
        src = (y == 0) ? Wq : (y == 1) ? Wk : (y == 2) ? Wv : Wo;
        dst = (y == 0) ? g_wqh : (y == 1) ? g_wkh : (y == 2) ? g_wvh : g_woh;
        base = 0;
    } else {
        src = x;
        dst = g_xh;
        base = (size_t)(y - 4) * (MT * DM / 4);
    }
    float4 v0 = ((const float4*)(src + base))[i];
    float4 v1 = ((const float4*)(src + base))[i + 131072];
    *(uint2*)(dst + base + (size_t)i * 4) =
        make_uint2(pack_h2(v0.x, v0.y), pack_h2(v0.z, v0.w));
    *(uint2*)(dst + base + (size_t)(i + 131072) * 4) =
        make_uint2(pack_h2(v1.x, v1.y), pack_h2(v1.z, v1.w));
}

// ---------------------------------------------------------------------------
// Single-pass fp16 tensor-core GEMM (fp32 acc): Y = A @ B^T.
// 128x128 CTA tile, BK=64, 3-stage cp.async, one sync per chunk.
// 256 threads = 8 warps, warp tile 64x32, 2 CTAs/SM.
// ---------------------------------------------------------------------------
constexpr int GSTAGE = 32768;
constexpr int GEMM_SMEM = 3 * GSTAGE;   // 98304

__device__ __forceinline__ void stage_load(
    uint32_t sbase, int st, const __half* __restrict__ Ah,
    const __half* __restrict__ Bh, int bm, int bn, int k0, int tid)
{
    const uint32_t base = sbase + st * GSTAGE;
#pragma unroll
    for (int i = 0; i < 8; i++) {
        int idx = tid + 256 * i;          // 0..2047
        int pl  = idx >> 10;              // 0:A 1:B
        int ci  = idx & 1023;
        int row = ci >> 3;                // 0..127
        int c   = ci & 7;                 // 16B chunk within 128B row
        const __half* src = pl ? Bh : Ah;
        int rowbase = pl ? bn : bm;
        cp_async16(base + pl * 16384 + atile_off(row, c),
                   src + (size_t)(rowbase + row) * 1024 + k0 + c * 8);
    }
}

__device__ __forceinline__ void mma_gemm_body(
    const __half* __restrict__ Ah, const __half* __restrict__ Bh,
    float* __restrict__ Yf32, const float* __restrict__ bias,
    __half* __restrict__ Yh, float oscale)
{
    extern __shared__ char smem[];
    const uint32_t sbase = smem_to_u32(smem);
    const int tid  = threadIdx.x;
    const int wid  = tid >> 5;
    const int lane = tid & 31;
    const int m_base = (wid & 1) * 64;    // 2 m-halves
    const int n_base = (wid >> 1) * 32;   // 4 n-quarters
    const int bm = blockIdx.y * 128;
    const int bn = blockIdx.x * 128;

    float acc[4][4][4];
#pragma unroll
    for (int mt = 0; mt < 4; mt++)
#pragma unroll
        for (int nt = 0; nt < 4; nt++)
#pragma unroll
            for (int i = 0; i < 4; i++) acc[mt][nt][i] = 0.f;

    stage_load(sbase, 0, Ah, Bh, bm, bn, 0, tid);  CP_COMMIT();
    stage_load(sbase, 1, Ah, Bh, bm, bn, 64, tid); CP_COMMIT();

    const int br  = lane & 7;
    const int bc0 = (lane >> 3) & 1;
    const int bro = (lane >> 4) << 3;

    for (int kc = 0; kc < 16; kc++) {
        if (kc < 15) cp_wait<1>(); else cp_wait<0>();
        __syncthreads();
        if (kc + 2 < 16) {
            stage_load(sbase, (kc + 2) % 3, Ah, Bh, bm, bn, (kc + 2) * 64, tid);
            CP_COMMIT();
        }

        const uint32_t st = sbase + (kc % 3) * GSTAGE;

        uint32_t bh[2][2][4];
#pragma unroll
        for (int ng = 0; ng < 2; ng++) {
            int row = n_base + ng * 16 + br + bro;
            ldmx4(bh[0][ng], st + 16384 + atile_off(row, bc0));
        }

#pragma unroll
        for (int s = 0; s < 4; s++) {
            uint32_t ah[4][4];
            {
                int r   = lane & 7;
                int sel = lane >> 3;
                int c   = 2 * s + (sel >> 1);
#pragma unroll
                for (int mt = 0; mt < 4; mt++) {
                    int row = m_base + mt * 16 + r + ((sel & 1) << 3);
                    ldmx4(ah[mt], st + atile_off(row, c));
                }
            }
            if (s < 3) {
                int c = 2 * (s + 1) + bc0;
#pragma unroll
                for (int ng = 0; ng < 2; ng++) {
                    int row = n_base + ng * 16 + br + bro;
                    ldmx4(bh[(s + 1) & 1][ng], st + 16384 + atile_off(row, c));
                }
            }
            const int cb = s & 1;
#pragma unroll
            for (int mt = 0; mt < 4; mt++)
#pragma unroll
                for (int nt = 0; nt < 4; nt++) {
                    int g = nt >> 1, o = (nt & 1) * 2;
                    mma16816(acc[mt][nt], ah[mt], bh[cb][g][o], bh[cb][g][o + 1]);
                }
        }
    }

    const int gid = lane >> 2;
    const int tig = lane & 3;
#pragma unroll
    for (int mt = 0; mt < 4; mt++) {
#pragma unroll
        for (int nt = 0; nt < 4; nt++) {
            int row0 = bm + m_base + mt * 16 + gid;
            int col0 = bn + n_base + nt * 8 + tig * 2;
            if (Yf32) {
                float b0 = bias ? bias[col0]     : 0.f;
                float b1 = bias ? bias[col0 + 1] : 0.f;
                float2 v0 = make_float2(acc[mt][nt][0] + b0, acc[mt][nt][1] + b1);
                float2 v1 = make_float2(acc[mt][nt][2] + b0, acc[mt][nt][3] + b1);
                *(float2*)(Yf32 + (size_t)row0 * 1024 + col0)       = v0;
                *(float2*)(Yf32 + (size_t)(row0 + 8) * 1024 + col0) = v1;
            } else {
                uint32_t h0 = pack_h2(acc[mt][nt][0] * oscale, acc[mt][nt][1] * oscale);
                uint32_t h1 = pack_h2(acc[mt][nt][2] * oscale, acc[mt][nt][3] * oscale);
                *(uint32_t*)(Yh + (size_t)row0 * 1024 + col0)       = h0;
                *(uint32_t*)(Yh + (size_t)(row0 + 8) * 1024 + col0) = h1;
            }
        }
    }
}

__global__ __launch_bounds__(256, 2) void qkv_mma() {
    if (blockIdx.z == 0)
        mma_gemm_body(g_xh, g_wqh, nullptr, nullptr, g_qh, QSCALE);
    else if (blockIdx.z == 1)
        mma_gemm_body(g_xh, g_wkh, nullptr, nullptr, g_kh, 1.f);
    else
        mma_gemm_body(g_xh, g_wvh, nullptr, nullptr, g_vh, 1.f);
}

__global__ __launch_bounds__(256, 2) void o_mma(const float* __restrict__ bo,
                                                float* __restrict__ out) {
    mma_gemm_body(g_ah, g_woh, out, bo, nullptr, 1.f);
}

// ---------------------------------------------------------------------------
// Single-pass fp16 causal flash attention (fp32-acc QK restored).
// grid = (S/128, B*H), 256 threads (8 warps, warp = 16 q rows), 2 CTAs/SM.
// Warps whose rows are entirely masked at tile t=2bx+1 skip its compute
// (exact no-op on m/l/o). Heavy blocks launched first.
// ---------------------------------------------------------------------------
constexpr int ASTAGE = 16384;
constexpr int ATTN_SMEM = 16384 + 3 * ASTAGE;  // 65536

__device__ __forceinline__ void attn_load_kv(uint32_t sb, int stage, int kv0,
                                             size_t headoff, int tid) {
#pragma unroll
    for (int i = 0; i < 4; i++) {
        int idx = tid + 256 * i;        // 0..1023
        int pl  = idx >> 9;             // 0:K 1:V
        int ci  = idx & 511;
        int r   = ci >> 3;
        int c   = ci & 7;
        const __half* base = pl ? g_vh : g_kh;
        cp_async16(sb + 16384 + stage * ASTAGE + pl * 8192 + atile_off(r, c),
                   base + headoff + (size_t)(kv0 + r) * DM + c * 8);
    }
    CP_COMMIT();
}

__global__ __launch_bounds__(256, 2) void attn_mma() {
    extern __shared__ char smem[];
    const uint32_t sb = smem_to_u32(smem);
    const int tid  = threadIdx.x;
    const int wid  = tid >> 5;
    const int lane = tid & 31;
    const int gid  = lane >> 2;
    const int tig  = lane & 3;
    const int bx   = gridDim.x - 1 - blockIdx.x;   // heavy blocks first
    const int bh   = blockIdx.y;
    const int b    = bh >> 4;
    const int h    = bh & 15;
    const int qb   = bx * 128;
    const int qw   = wid * 16;
    const size_t headoff = (size_t)(b * SS) * DM + h * 64;

#pragma unroll
    for (int i = 0; i < 4; i++) {
        int idx = tid + 256 * i;
        int r   = idx >> 3;
        int c   = idx & 7;
        cp_async16(sb + atile_off(r, c),
                   g_qh + headoff + (size_t)(qb + r) * DM + c * 8);
    }
    CP_COMMIT();

    float o[8][4];
#pragma unroll
    for (int nt = 0; nt < 8; nt++)
#pragma unroll
        for (int i = 0; i < 4; i++) o[nt][i] = 0.f;
    float m0 = -1e30f, m1 = -1e30f, l0 = 0.f, l1 = 0.f;

    const int ntiles = 2 * bx + 2;
    attn_load_kv(sb, 0, 0, headoff, tid);
    attn_load_kv(sb, 1, 64, headoff, tid);

    for (int t = 0; t < ntiles; t++) {
        if (t + 1 < ntiles) cp_wait<1>(); else cp_wait<0>();
        __syncthreads();
        if (t + 2 < ntiles)
            attn_load_kv(sb, (t + 2) % 3, (t + 2) * 64, headoff, tid);

        // Warps 0..3 (rows qw..qw+15 < 64) are fully masked at the second
        // diagonal tile: processing it is an exact no-op on (m,l,o). Skip.
        if (t == 2 * bx + 1 && wid < 4) continue;

        const uint32_t kst = sb + 16384 + (t % 3) * ASTAGE;

        float sf[8][4];
#pragma unroll
        for (int jt = 0; jt < 8; jt++)
#pragma unroll
            for (int i = 0; i < 4; i++) sf[jt][i] = 0.f;

        // ---- S = Q * K^T (log2 units), fp32 acc ----
#pragma unroll
        for (int kc = 0; kc < 4; kc++) {
            uint32_t qh[4];
            {
                int r = lane & 7, sel = lane >> 3;
                int row = qw + r + ((sel & 1) << 3);
                int c = kc * 2 + (sel >> 1);
                ldmx4(qh, sb + atile_off(row, c));
            }
#pragma unroll
            for (int g2 = 0; g2 < 4; g2++) {
                uint32_t kh[4];
                {
                    int r = lane & 7;
                    int row = g2 * 16 + r + ((lane >> 4) << 3);
                    int c = kc * 2 + ((lane >> 3) & 1);
                    ldmx4(kh, kst + atile_off(row, c));
                }
                mma16816(sf[g2 * 2 + 0], qh, kh[0], kh[1]);
                mma16816(sf[g2 * 2 + 1], qh, kh[2], kh[3]);
            }
        }

        // ---- causal mask (diagonal tiles only) ----
        if (t >= 2 * bx) {
            const int kv0 = t * 64;
            const int r0 = qb + qw + gid, r1 = r0 + 8;
#pragma unroll
            for (int jt = 0; jt < 8; jt++) {
                int col = kv0 + jt * 8 + tig * 2;
                if (col     > r0) sf[jt][0] = -1e30f;
                if (col + 1 > r0) sf[jt][1] = -1e30f;
                if (col     > r1) sf[jt][2] = -1e30f;
                if (col + 1 > r1) sf[jt][3] = -1e30f;
            }
        }

        // ---- online softmax (base-2), f16x2 exp ----
        float tm0 = -1e30f, tm1 = -1e30f;
#pragma unroll
        for (int jt = 0; jt < 8; jt++) {
            tm0 = fmaxf(tm0, fmaxf(sf[jt][0], sf[jt][1]));
            tm1 = fmaxf(tm1, fmaxf(sf[jt][2], sf[jt][3]));
        }
        uint32_t tm2 = pack_h2(tm0, tm1);
        tm2 = hmax2u(tm2, __shfl_xor_sync(0xFFFFFFFFu, tm2, 1));
        tm2 = hmax2u(tm2, __shfl_xor_sync(0xFFFFFFFFu, tm2, 2));
        float2 tmf = h2f2(tm2);

        float mn0 = fmaxf(fmaxf(m0, tmf.x), -1e4f);
        float mn1 = fmaxf(fmaxf(m1, tmf.y), -1e4f);
        float c0 = ex2f(m0 - mn0);
        float c1 = ex2f(m1 - mn1);
        m0 = mn0; m1 = mn1;

        uint32_t ph[16];
        float rs0 = 0.f, rs1 = 0.f;
#pragma unroll
        for (int jt = 0; jt < 8; jt++) {
            uint32_t p01 = h2ex2(pack_h2(sf[jt][0] - mn0, sf[jt][1] - mn0));
            uint32_t p23 = h2ex2(pack_h2(sf[jt][2] - mn1, sf[jt][3] - mn1));
            ph[jt * 2]     = p01;
            ph[jt * 2 + 1] = p23;
            float2 f01 = h2f2(p01);
            float2 f23 = h2f2(p23);
            rs0 += f01.x + f01.y;
            rs1 += f23.x + f23.y;
        }
        rs0 += __shfl_xor_sync(0xFFFFFFFFu, rs0, 1);
        rs0 += __shfl_xor_sync(0xFFFFFFFFu, rs0, 2);
        rs1 += __shfl_xor_sync(0xFFFFFFFFu, rs1, 1);
        rs1 += __shfl_xor_sync(0xFFFFFFFFu, rs1, 2);
        l0 = l0 * c0 + rs0;
        l1 = l1 * c1 + rs1;

#pragma unroll
        for (int nt = 0; nt < 8; nt++) {
            o[nt][0] *= c0; o[nt][1] *= c0;
            o[nt][2] *= c1; o[nt][3] *= c1;
        }

        // ---- O += P * V (fp32 acc) ----
#pragma unroll
        for (int kc = 0; kc < 4; kc++) {
            uint32_t pa[4] = {ph[4 * kc], ph[4 * kc + 1],
                              ph[4 * kc + 2], ph[4 * kc + 3]};
#pragma unroll
            for (int dg = 0; dg < 4; dg++) {
                uint32_t vh[4];
                {
                    int r = lane & 7;
                    int row = kc * 16 + r + (((lane >> 3) & 1) << 3);
                    int c = dg * 2 + (lane >> 4);
                    ldmx4t(vh, kst + 8192 + atile_off(row, c));
                }
                mma16816(o[dg * 2 + 0], pa, vh[0], vh[1]);
                mma16816(o[dg * 2 + 1], pa, vh[2], vh[3]);
            }
        }
    }

    const float inv0 = 1.f / l0;
    const float inv1 = 1.f / l1;
    const size_t tok0 = (size_t)(b * SS + qb + qw + gid) * DM;
#pragma unroll
    for (int nt = 0; nt < 8; nt++) {
        int col = h * 64 + nt * 8 + tig * 2;
        *(uint32_t*)(g_ah + tok0 + col) =
            pack_h2(o[nt][0] * inv0, o[nt][1] * inv0);
        *(uint32_t*)(g_ah + tok0 + 8 * DM + col) =
            pack_h2(o[nt][2] * inv1, o[nt][3] * inv1);
    }
}

// ---------------------------------------------------------------------------
extern "C" void kernel_launch(void* const* d_in, const int* in_sizes, int n_in,
                              void* d_out, int out_size)
{
    const float* x  = (const float*)d_in[0];
    const float* Wq = (const float*)d_in[1];
    const float* Wk = (const float*)d_in[2];
    const float* Wv = (const float*)d_in[3];
    const float* Wo = (const float*)d_in[4];
    const float* bo = (const float*)d_in[5];
    float* out = (float*)d_out;

    cudaFuncSetAttribute(qkv_mma,  cudaFuncAttributeMaxDynamicSharedMemorySize, GEMM_SMEM);
    cudaFuncSetAttribute(o_mma,    cudaFuncAttributeMaxDynamicSharedMemorySize, GEMM_SMEM);
    cudaFuncSetAttribute(attn_mma, cudaFuncAttributeMaxDynamicSharedMemorySize, ATTN_SMEM);

    cvt_all<<<dim3(512, 8), 256>>>(x, Wq, Wk, Wv, Wo);

    dim3 gqkv(DM / 128, MT / 128, 3);
    qkv_mma<<<gqkv, 256, GEMM_SMEM>>>();

    dim3 gattn(SS / 128, BB * NH);
    attn_mma<<<gattn, 256, ATTN_SMEM>>>();

    dim3 go(DM / 128, MT / 128);
    o_mma<<<go, 256, GEMM_SMEM>>>(bo, out);
}